// round 15
// baseline (speedup 1.0000x reference)
#include <cuda_runtime.h>

// Problem constants (LatentCoulombLongRange: N=8192, F=128, H=64, B=8)
#define MAXN 8192
#define FDIM 128
#define HDIM 64
#define MAXB 64
#define NSLOT 32            // charge-sum slots per graph
#define GRID  296           // 2 blocks/SM x 148 SMs — all co-resident (required!)
#define NWARP (GRID * 8)    // pair-phase warps

// Scratch (allocation-free rule: __device__ globals; zero-initialized at load)
__device__ float        d_qraw[MAXN];
__device__ float4       d_qpos[MAXN];          // {x, y, z, centered q}
__device__ int          d_gstart[MAXB];
__device__ int          d_gend[MAXB];
__device__ float        d_gsum[MAXB * NSLOT];  // zeroed in phase C each replay
__device__ unsigned int d_sync0, d_sync1;      // monotonic ticket counters

// ---- raw single-MUFU intrinsics ----
__device__ __forceinline__ float fast_rsqrt(float x) {
    float r; asm("rsqrt.approx.ftz.f32 %0, %1;" : "=f"(r) : "f"(x)); return r;
}
__device__ __forceinline__ float fast_ex2(float x) {
    float r; asm("ex2.approx.ftz.f32 %0, %1;" : "=f"(r) : "f"(x)); return r;
}
__device__ __forceinline__ float fast_rcp(float x) {
    float r; asm("rcp.approx.ftz.f32 %0, %1;" : "=f"(r) : "f"(x)); return r;
}
#define LOG2E 1.44269504088896f
__device__ __forceinline__ float silu_f(float v) {
    return v * fast_rcp(1.0f + fast_ex2(-LOG2E * v));
}

// Grid-wide ticket barrier: monotonic counter, replay-safe (no resets).
// All GRID blocks are co-resident by construction, so spinning is safe.
__device__ __forceinline__ void gridsync(unsigned int* c) {
    __syncthreads();
    __threadfence();
    if (threadIdx.x == 0) {
        unsigned int t = atomicAdd(c, 1u);
        unsigned int target = (t / GRID + 1u) * GRID;
        unsigned int v;
        do {
            asm volatile("ld.acquire.gpu.u32 %0, [%1];" : "=r"(v) : "l"(c));
        } while (v < target);
    }
    __syncthreads();
}

__device__ __forceinline__ float pair_term(float4 pj, float4 pi,
                                           float soft2, float nl, float& k_out) {
    float dx = pj.x - pi.x;
    float dy = pj.y - pi.y;
    float dz = pj.z - pi.z;
    float r2 = fmaf(dx, dx, fmaf(dy, dy, fmaf(dz, dz, soft2)));
    float rinv = fast_rsqrt(r2);
    float r = r2 * rinv;
    k_out = fast_ex2(nl * r) * rinv;
    return pj.w;
}

// ---------------------------------------------------------------------------
// ONE persistent kernel: Phase A (MLP GEMM, 32x64 tiles) -> gridsync ->
// Phase B (slot-reduce means + pack qpos) -> gridsync -> Phase C (pair sum).
// ---------------------------------------------------------------------------
__global__ __launch_bounds__(256, 2)
void fused_kernel(const float* __restrict__ x,
                  const float* __restrict__ pos,
                  const float* __restrict__ W1,
                  const float* __restrict__ b1,
                  const float* __restrict__ W2,
                  const float* __restrict__ b2,
                  const float* __restrict__ scr_p,
                  const float* __restrict__ soft_p,
                  const int* __restrict__ batch,
                  float* __restrict__ out, int n, int nb) {
    __shared__ float xs[64][34];   // 8.5 KB
    __shared__ float ws[64][64];   // 16 KB
    __shared__ float smean[MAXB];  // 256 B

    int t   = threadIdx.x;
    int bid = blockIdx.x;

    // ================= Phase A: charge-head MLP (32-atom x 64-h GEMM tile) ==
    int ntiles = (n + 31) / 32;
    if (bid < ntiles) {
        int tx = t & 15, ty = t >> 4;          // tx 0..15, ty 0..15
        int base = bid * 32;
        int m0 = ty * 2, h0 = tx * 4;

        float acc[2][4] = {{0.f,0.f,0.f,0.f},{0.f,0.f,0.f,0.f}};
        const float4* xv4  = (const float4*)x;
        const float4* w1v4 = (const float4*)W1;

        for (int kc = 0; kc < FDIM; kc += 64) {
            {   // stage x chunk transposed
                int a  = t >> 3;               // 0..31
                int u0 = t & 7;
                int arow = min(base + a, n - 1);
#pragma unroll
                for (int it = 0; it < 2; it++) {
                    int u = u0 + it * 8;
                    float4 v = xv4[arow * (FDIM / 4) + (kc >> 2) + u];
                    xs[4 * u + 0][a] = v.x;
                    xs[4 * u + 1][a] = v.y;
                    xs[4 * u + 2][a] = v.z;
                    xs[4 * u + 3][a] = v.w;
                }
            }
            {   // stage W1 chunk
#pragma unroll
                for (int it = 0; it < 4; it++) {
                    int idx = t + it * 256;
                    int kl = idx >> 4, c4 = idx & 15;
                    *(float4*)&ws[kl][c4 * 4] = w1v4[(kc + kl) * (HDIM / 4) + c4];
                }
            }
            __syncthreads();

#pragma unroll 16
            for (int k = 0; k < 64; k++) {
                float2 xf = *(const float2*)&xs[k][m0];
                float4 wf = *(const float4*)&ws[k][h0];
                acc[0][0] = fmaf(xf.x, wf.x, acc[0][0]);
                acc[0][1] = fmaf(xf.x, wf.y, acc[0][1]);
                acc[0][2] = fmaf(xf.x, wf.z, acc[0][2]);
                acc[0][3] = fmaf(xf.x, wf.w, acc[0][3]);
                acc[1][0] = fmaf(xf.y, wf.x, acc[1][0]);
                acc[1][1] = fmaf(xf.y, wf.y, acc[1][1]);
                acc[1][2] = fmaf(xf.y, wf.z, acc[1][2]);
                acc[1][3] = fmaf(xf.y, wf.w, acc[1][3]);
            }
            __syncthreads();
        }

        // epilogue: SiLU + W2 contraction, reduce over tx, publish
        float4 b1v = ((const float4*)b1)[tx];
        float4 w2v = ((const float4*)W2)[tx];
        float part[2];
#pragma unroll
        for (int a = 0; a < 2; a++) {
            float p;
            p = silu_f(acc[a][0] + b1v.x) * w2v.x;
            p = fmaf(silu_f(acc[a][1] + b1v.y), w2v.y, p);
            p = fmaf(silu_f(acc[a][2] + b1v.z), w2v.z, p);
            p = fmaf(silu_f(acc[a][3] + b1v.w), w2v.w, p);
            part[a] = p;
        }
#pragma unroll
        for (int off = 1; off < 16; off <<= 1) {
#pragma unroll
            for (int a = 0; a < 2; a++)
                part[a] += __shfl_xor_sync(0xffffffffu, part[a], off);
        }

        if (tx == 0) {
            float bias = b2[0];
#pragma unroll
            for (int a = 0; a < 2; a++) {
                int i = base + m0 + a;
                if (i < n) {
                    float qi = part[a] + bias;
                    d_qraw[i] = qi;
                    int g = batch[i];
                    atomicAdd(&d_gsum[g * NSLOT + (i & (NSLOT - 1))], qi);
                    if (i == 0     || batch[i - 1] != g) d_gstart[g] = i;
                    if (i == n - 1 || batch[i + 1] != g) d_gend[g]   = i + 1;
                }
            }
        }
    }

    gridsync(&d_sync0);

    // ================= Phase B: per-graph means + pack qpos ================
    if (t < MAXB) smean[t] = 0.0f;
    __syncthreads();
    for (int s = t; s < nb * NSLOT; s += 256)
        atomicAdd(&smean[s / NSLOT], d_gsum[s]);
    __syncthreads();
    if (t < nb) {
        float c = (float)max(1, d_gend[t] - d_gstart[t]);
        smean[t] = smean[t] / c;
    }
    __syncthreads();

    for (int i = bid * 256 + t; i < n; i += GRID * 256) {
        int g = batch[i];
        float qc = d_qraw[i] - smean[g];
        d_qpos[i] = make_float4(pos[3 * i], pos[3 * i + 1], pos[3 * i + 2], qc);
    }

    gridsync(&d_sync1);

    // ================= Phase C: pair sum (+ d_gsum reset for next replay) ==
    {
        int gt = bid * 256 + t;
        if (gt < MAXB * NSLOT) d_gsum[gt] = 0.0f;
    }

    const float4* __restrict__ qp = d_qpos;
    float scr   = *scr_p;
    float soft  = *soft_p;
    float soft2 = soft * soft;
    const float nl = -scr * LOG2E;

    int warp = t >> 5, lane = t & 31;
    for (int i = bid * 8 + warp; i < n; i += NWARP) {
        int g  = batch[i];
        int gs = d_gstart[g];
        int ge = d_gend[g];
        int len   = ge - gs;
        int nfull = len >> 7;

        float4 pi = qp[i];
        float acc = 0.0f;

        const float4* p = qp + gs + lane;
        for (int it = 0; it < nfull; it++) {
            float4 p0 = p[0];
            float4 p1 = p[32];
            float4 p2 = p[64];
            float4 p3 = p[96];
            float k0, k1, k2, k3;
            float q0 = pair_term(p0, pi, soft2, nl, k0);
            float q1 = pair_term(p1, pi, soft2, nl, k1);
            float q2 = pair_term(p2, pi, soft2, nl, k2);
            float q3 = pair_term(p3, pi, soft2, nl, k3);
            acc = fmaf(q0, k0, acc);
            acc = fmaf(q1, k1, acc);
            acc = fmaf(q2, k2, acc);
            acc = fmaf(q3, k3, acc);
            p += 128;
        }
        for (int j = gs + (nfull << 7) + lane; j < ge; j += 32) {
            float4 pj = qp[j];
            float kk;
            float qw = pair_term(pj, pi, soft2, nl, kk);
            acc = fmaf(qw, kk, acc);
        }

        if (lane == 0) {
            float ks;
            float qs = pair_term(pi, pi, soft2, nl, ks);
            acc -= qs * ks;
        }

#pragma unroll
        for (int off = 16; off; off >>= 1)
            acc += __shfl_down_sync(0xffffffffu, acc, off);

        if (lane == 0) out[i] = 0.5f * pi.w * acc;
    }
}

// ---------------------------------------------------------------------------
// launch
// inputs: 0:x 1:pos 2:cell 3:W1 4:b1 5:W2 6:b2 7:screening 8:softening 9:batch
// ---------------------------------------------------------------------------
extern "C" void kernel_launch(void* const* d_in, const int* in_sizes, int n_in,
                              void* d_out, int out_size) {
    const float* x     = (const float*)d_in[0];
    const float* pos   = (const float*)d_in[1];
    const float* W1    = (const float*)d_in[3];
    const float* b1    = (const float*)d_in[4];
    const float* W2    = (const float*)d_in[5];
    const float* b2    = (const float*)d_in[6];
    const float* scr   = (const float*)d_in[7];
    const float* soft  = (const float*)d_in[8];
    const int*   batch = (const int*)d_in[9];
    float* out = (float*)d_out;

    int n  = in_sizes[9];          // N atoms
    int nb = in_sizes[2] / 9;      // B graphs (cell is [B,3,3])
    if (nb > MAXB) nb = MAXB;

    fused_kernel<<<GRID, 256>>>(x, pos, W1, b1, W2, b2, scr, soft, batch,
                                out, n, nb);
}

// round 16
// speedup vs baseline: 1.1837x; 1.1837x over previous
#include <cuda_runtime.h>

// Problem constants (LatentCoulombLongRange: N=8192, F=128, H=64, B=8)
#define MAXN 8192
#define FDIM 128
#define HDIM 64
#define MAXB 64
#define NSLOT 32          // charge-sum slots per graph

// SMEM row strides (words) chosen for conflict-free fragment LDS:
//  xs: rows of 132 (132 mod 32 = 4 -> banks 4g+c distinct for g<8,c<4)
//  wh: rows of 72  (72 mod 32 = 8 -> banks 8c+g distinct for c<4,g<8)
#define XS_RS 132
#define WH_RS 72

// Scratch (allocation-free rule: __device__ globals; zero-initialized at load)
__device__ float  d_qraw[MAXN];
__device__ float4 d_qpos[MAXN];            // {x, y, z, centered q}
__device__ int    d_gstart[MAXB];
__device__ int    d_gend[MAXB];
__device__ float  d_gsum[MAXB * NSLOT];    // slotted sums; re-zeroed by pair_kernel

// ---- raw single-MUFU intrinsics ----
__device__ __forceinline__ float fast_rsqrt(float x) {
    float r; asm("rsqrt.approx.ftz.f32 %0, %1;" : "=f"(r) : "f"(x)); return r;
}
__device__ __forceinline__ float fast_ex2(float x) {
    float r; asm("ex2.approx.ftz.f32 %0, %1;" : "=f"(r) : "f"(x)); return r;
}
__device__ __forceinline__ float fast_rcp(float x) {
    float r; asm("rcp.approx.ftz.f32 %0, %1;" : "=f"(r) : "f"(x)); return r;
}
#define LOG2E 1.44269504088896f
__device__ __forceinline__ float silu_f(float v) {
    return v * fast_rcp(1.0f + fast_ex2(-LOG2E * v));
}

// tf32 helpers
__device__ __forceinline__ unsigned int to_tf32(float f) {
    unsigned int u; asm("cvt.rna.tf32.f32 %0, %1;" : "=r"(u) : "f"(f)); return u;
}
__device__ __forceinline__ void mma_tf32(float* d,
                                         unsigned int a0, unsigned int a1,
                                         unsigned int a2, unsigned int a3,
                                         unsigned int b0, unsigned int b1) {
    asm volatile(
        "mma.sync.aligned.m16n8k8.row.col.f32.tf32.tf32.f32 "
        "{%0,%1,%2,%3}, {%4,%5,%6,%7}, {%8,%9}, {%0,%1,%2,%3};"
        : "+f"(d[0]), "+f"(d[1]), "+f"(d[2]), "+f"(d[3])
        : "r"(a0), "r"(a1), "r"(a2), "r"(a3), "r"(b0), "r"(b1));
}

// ---------------------------------------------------------------------------
// K1: charge-head MLP via tf32 tensor cores (3xTF32: hi*hi + hi*lo + lo*hi).
//     Block = 256 thr / 8 warps; tile 64 atoms x 64 H; grid = 128.
//     Warp w: atoms 16*(w&3).., H-half 32*(w>>2).. -> 4 m16n8 C tiles.
//     K = 128 as 16 k8 steps. Epilogue: SiLU + W2 dot per element, quad
//     shfl-reduce, SMEM atomic combine across the 2 H-half warps.
// ---------------------------------------------------------------------------
__global__ __launch_bounds__(256)
void mlp_kernel(const float* __restrict__ x,
                const float* __restrict__ W1,
                const float* __restrict__ b1,
                const float* __restrict__ W2,
                const float* __restrict__ b2,
                const int* __restrict__ batch,
                int n) {
    __shared__ float xs[64 * XS_RS];   // 33.8 KB: x tile, row-major [atom][k]
    __shared__ float wh[FDIM * WH_RS]; // 36.9 KB: W1, row-major [k][h]
    __shared__ float sq[64];           // per-atom q partial combine

    int t    = threadIdx.x;
    int base = blockIdx.x * 64;

    if (t < 64) sq[t] = 0.0f;

    // stage x tile: 64 atoms x 32 float4 = 2048 f4, 8 per thread
    {
        const float4* xv4 = (const float4*)x;
#pragma unroll
        for (int it = 0; it < 8; it++) {
            int idx = t + it * 256;            // 0..2047
            int row = idx >> 5, c4 = idx & 31;
            int arow = min(base + row, n - 1);
            *(float4*)&xs[row * XS_RS + c4 * 4] = xv4[arow * 32 + c4];
        }
    }
    // stage W1: 128 rows x 16 float4 = 2048 f4, 8 per thread
    {
        const float4* w1v4 = (const float4*)W1;
#pragma unroll
        for (int it = 0; it < 8; it++) {
            int idx = t + it * 256;
            int row = idx >> 4, c4 = idx & 15;
            *(float4*)&wh[row * WH_RS + c4 * 4] = w1v4[row * 16 + c4];
        }
    }
    __syncthreads();

    int w    = t >> 5;
    int lane = t & 31;
    int g    = lane >> 2;      // 0..7
    int c    = lane & 3;       // 0..3
    int m_base = 16 * (w & 3); // local atom base (0,16,32,48)
    int n_base = 32 * (w >> 2);// H half (0 or 32)

    float d[4][4] = {{0,0,0,0},{0,0,0,0},{0,0,0,0},{0,0,0,0}};

    const float* xsp = xs + (m_base + g) * XS_RS + c;
    const float* whp = wh + c * WH_RS + n_base + g;

#pragma unroll
    for (int k = 0; k < 16; k++) {
        int xo = k * 8;
        // A fragment (16x8), rows m_base+g / +8, cols k8+c / +4
        float a0f = xsp[xo];
        float a1f = xsp[8 * XS_RS + xo];
        float a2f = xsp[xo + 4];
        float a3f = xsp[8 * XS_RS + xo + 4];
        unsigned int ah0 = to_tf32(a0f), ah1 = to_tf32(a1f),
                     ah2 = to_tf32(a2f), ah3 = to_tf32(a3f);
        unsigned int al0 = to_tf32(a0f - __uint_as_float(ah0));
        unsigned int al1 = to_tf32(a1f - __uint_as_float(ah1));
        unsigned int al2 = to_tf32(a2f - __uint_as_float(ah2));
        unsigned int al3 = to_tf32(a3f - __uint_as_float(ah3));

        int wo = k * 8 * WH_RS;
#pragma unroll
        for (int nt = 0; nt < 4; nt++) {
            // B fragment (8x8): rows k8+c / +4, col n_base + nt*8 + g
            float b0f = whp[wo + nt * 8];
            float b1f = whp[wo + 4 * WH_RS + nt * 8];
            unsigned int bh0 = to_tf32(b0f), bh1 = to_tf32(b1f);
            unsigned int bl0 = to_tf32(b0f - __uint_as_float(bh0));
            unsigned int bl1 = to_tf32(b1f - __uint_as_float(bh1));
            mma_tf32(d[nt], ah0, ah1, ah2, ah3, bh0, bh1);  // hi*hi
            mma_tf32(d[nt], ah0, ah1, ah2, ah3, bl0, bl1);  // hi*lo
            mma_tf32(d[nt], al0, al1, al2, al3, bh0, bh1);  // lo*hi
        }
    }

    // Epilogue: this thread holds rows {m_base+g, m_base+g+8},
    // cols per nt: {n_base+nt*8+2c, +1}. Apply SiLU + W2 dot.
    float part0 = 0.0f, part1 = 0.0f;
#pragma unroll
    for (int nt = 0; nt < 4; nt++) {
        int col = n_base + nt * 8 + 2 * c;
        float bi0 = b1[col],     bi1 = b1[col + 1];
        float w20 = W2[col],     w21 = W2[col + 1];
        part0 = fmaf(silu_f(d[nt][0] + bi0), w20, part0);
        part0 = fmaf(silu_f(d[nt][1] + bi1), w21, part0);
        part1 = fmaf(silu_f(d[nt][2] + bi0), w20, part1);
        part1 = fmaf(silu_f(d[nt][3] + bi1), w21, part1);
    }
    // reduce over the quad (c = 0..3 covers all 8 cols of each n-tile)
#pragma unroll
    for (int off = 1; off < 4; off <<= 1) {
        part0 += __shfl_xor_sync(0xffffffffu, part0, off);
        part1 += __shfl_xor_sync(0xffffffffu, part1, off);
    }
    if (c == 0) {   // one lane per row-group: combine the 2 H-half warps
        atomicAdd(&sq[m_base + g],     part0);
        atomicAdd(&sq[m_base + g + 8], part1);
    }
    __syncthreads();

    // finalize: q, slotted per-graph sums, sorted-batch boundaries
    if (t < 64) {
        int i = base + t;
        if (i < n) {
            float qi = sq[t] + b2[0];
            d_qraw[i] = qi;
            int gg = batch[i];
            atomicAdd(&d_gsum[gg * NSLOT + (i & (NSLOT - 1))], qi);
            if (i == 0     || batch[i - 1] != gg) d_gstart[gg] = i;
            if (i == n - 1 || batch[i + 1] != gg) d_gend[gg]   = i + 1;
        }
    }
}

// ---------------------------------------------------------------------------
// K2: pack {pos, centered q} into float4 (R14 verbatim).
// ---------------------------------------------------------------------------
__global__ void pack_kernel(const float* __restrict__ pos,
                            const int* __restrict__ batch, int n, int nb) {
    __shared__ float smean[MAXB];
    int t = threadIdx.x;
    if (t < MAXB) smean[t] = 0.0f;
    __syncthreads();
    for (int s = t; s < nb * NSLOT; s += 256)
        atomicAdd(&smean[s / NSLOT], d_gsum[s]);
    __syncthreads();

    int i = blockIdx.x * 256 + t;
    if (i < n) {
        int g = batch[i];
        float cnt  = (float)max(1, d_gend[g] - d_gstart[g]);
        float mean = smean[g] / cnt;
        float qc = d_qraw[i] - mean;
        d_qpos[i] = make_float4(pos[3 * i], pos[3 * i + 1], pos[3 * i + 2], qc);
    }
}

// ---------------------------------------------------------------------------
// K3: screened Coulomb pair sum (R14 verbatim: clamp-free main + tail).
// ---------------------------------------------------------------------------
__device__ __forceinline__ float pair_term(float4 pj, float4 pi,
                                           float soft2, float nl, float& k_out) {
    float dx = pj.x - pi.x;
    float dy = pj.y - pi.y;
    float dz = pj.z - pi.z;
    float r2 = fmaf(dx, dx, fmaf(dy, dy, fmaf(dz, dz, soft2)));
    float rinv = fast_rsqrt(r2);
    float r = r2 * rinv;
    k_out = fast_ex2(nl * r) * rinv;
    return pj.w;
}

__global__ void pair_kernel(const int* __restrict__ batch,
                            const float* __restrict__ scr_p,
                            const float* __restrict__ soft_p,
                            float* __restrict__ out, int n) {
    if (blockIdx.x == 0) {
#pragma unroll
        for (int s = threadIdx.x; s < MAXB * NSLOT; s += 256)
            d_gsum[s] = 0.0f;
    }

    int i    = (blockIdx.x * blockDim.x + threadIdx.x) >> 5;
    int lane = threadIdx.x & 31;
    if (i >= n) return;

    const float4* __restrict__ qp = d_qpos;

    float scr   = *scr_p;
    float soft  = *soft_p;
    float soft2 = soft * soft;
    const float nl = -scr * LOG2E;

    int g  = batch[i];
    int gs = d_gstart[g];
    int ge = d_gend[g];
    int len   = ge - gs;
    int nfull = len >> 7;

    float4 pi = qp[i];
    float acc = 0.0f;

    const float4* p = qp + gs + lane;
    for (int it = 0; it < nfull; it++) {
        float4 p0 = p[0];
        float4 p1 = p[32];
        float4 p2 = p[64];
        float4 p3 = p[96];
        float k0, k1, k2, k3;
        float q0 = pair_term(p0, pi, soft2, nl, k0);
        float q1 = pair_term(p1, pi, soft2, nl, k1);
        float q2 = pair_term(p2, pi, soft2, nl, k2);
        float q3 = pair_term(p3, pi, soft2, nl, k3);
        acc = fmaf(q0, k0, acc);
        acc = fmaf(q1, k1, acc);
        acc = fmaf(q2, k2, acc);
        acc = fmaf(q3, k3, acc);
        p += 128;
    }
    for (int j = gs + (nfull << 7) + lane; j < ge; j += 32) {
        float4 pj = qp[j];
        float kk;
        float qw = pair_term(pj, pi, soft2, nl, kk);
        acc = fmaf(qw, kk, acc);
    }

    if (lane == 0) {
        float ks;
        float qs = pair_term(pi, pi, soft2, nl, ks);
        acc -= qs * ks;
    }

#pragma unroll
    for (int off = 16; off; off >>= 1)
        acc += __shfl_down_sync(0xffffffffu, acc, off);

    if (lane == 0) out[i] = 0.5f * pi.w * acc;
}

// ---------------------------------------------------------------------------
// launch
// inputs: 0:x 1:pos 2:cell 3:W1 4:b1 5:W2 6:b2 7:screening 8:softening 9:batch
// ---------------------------------------------------------------------------
extern "C" void kernel_launch(void* const* d_in, const int* in_sizes, int n_in,
                              void* d_out, int out_size) {
    const float* x     = (const float*)d_in[0];
    const float* pos   = (const float*)d_in[1];
    const float* W1    = (const float*)d_in[3];
    const float* b1    = (const float*)d_in[4];
    const float* W2    = (const float*)d_in[5];
    const float* b2    = (const float*)d_in[6];
    const float* scr   = (const float*)d_in[7];
    const float* soft  = (const float*)d_in[8];
    const int*   batch = (const int*)d_in[9];
    float* out = (float*)d_out;

    int n  = in_sizes[9];
    int nb = in_sizes[2] / 9;
    if (nb > MAXB) nb = MAXB;

    mlp_kernel<<<(n + 63) / 64, 256>>>(x, W1, b1, W2, b2, batch, n);
    pack_kernel<<<(n + 255) / 256, 256>>>(pos, batch, n, nb);
    int threads = 256;
    int blocks  = (n * 32 + threads - 1) / threads;
    pair_kernel<<<blocks, threads>>>(batch, scr, soft, out, n);
}